// round 4
// baseline (speedup 1.0000x reference)
#include <cuda_runtime.h>
#include <cuda_bf16.h>

// Balloon-Windkessel BOLD, explicit Euler, T=1000 steps, B=16384 sims.
// R4: TWO sims per thread (adjacent columns 2g, 2g+1):
//  - per-sim arithmetic BIT-IDENTICAL to R1/R3 (rel_err 1.39e-4) — pure
//    scheduling change: two independent chains give the in-order issue
//    window real ILP (1 warp/SMSP has no TLP to hide latency otherwise).
//  - noise load becomes LDG.64, output store STG.64 -> memory issue slots
//    and addressing per sim halve.
//  - look-ahead of E(f), f*ib, f-1, -sigma*s keeps MUFU off carried paths.
//  - 128 blocks x 64 threads: 256 warps spread over 128 SMs (SMSP 0/1),
//    minimizing per-SM LSU pressure. U=10 ping-pong prefetch (~600+ cyc
//    load-to-use).

#define DT_C        0.01f
#define V0_C        0.02f
#define NOISE_AMP_C 0.01f
#define BATCH_C     16384

__device__ __forceinline__ float fast_rcp(float x) {
    float r; asm("rcp.approx.f32 %0, %1;" : "=f"(r) : "f"(x)); return r;
}
__device__ __forceinline__ float fast_ex2(float x) {
    float r; asm("ex2.approx.f32 %0, %1;" : "=f"(r) : "f"(x)); return r;
}

struct BWState {
    float s, f, v, q;
    float E;    // 1 - (1-beta)^(1/f)   (for current f)
    float fib;  // f * (1/beta)
    float fm1;  // f - 1
    float nss;  // -sigma * s
};

struct BWConst {
    float sigma, mu, ib, c_vl, l2mb;
    float psi, phi, chi;
};

__device__ __forceinline__ void bw_seed(BWState& st, const BWConst& C) {
    st.s = 0.0f; st.f = 1.0f; st.v = 1.0f; st.q = 1.0f;
    const float rf = fast_rcp(st.f);
    st.E   = 1.0f - fast_ex2(C.l2mb * rf);
    st.fib = st.f * C.ib;
    st.fm1 = st.f - 1.0f;
    st.nss = -C.sigma * st.s;
}

// One Euler step; arithmetic identical to R1/R3.
__device__ __forceinline__ float bw_step(BWState& st, const BWConst& C, float z)
{
    const float s2 = fmaf(DT_C, fmaf(NOISE_AMP_C, z,
                              fmaf(-C.mu, st.fm1, st.nss)), st.s);
    const float f2 = fmaf(DT_C, st.s, st.f);
    const float v2 = fmaf(C.c_vl, st.f - st.v, st.v);
    const float q2 = fmaf(C.c_vl, fmaf(st.fib, st.E, -st.q), st.q);

    const float rf = fast_rcp(f2);
    st.E   = 1.0f - fast_ex2(C.l2mb * rf);
    st.fib = f2 * C.ib;
    st.fm1 = f2 - 1.0f;
    st.nss = -C.sigma * s2;

    const float rv = fast_rcp(v2);
    const float y  = V0_C * fmaf(C.phi, 1.0f - q2,
                          fmaf(C.psi, fmaf(-q2, rv, 1.0f),
                               C.chi * (1.0f - v2)));
    st.s = s2; st.f = f2; st.v = v2; st.q = q2;
    return y;
}

template<int U, int BS>
__global__ __launch_bounds__(64, 1)
void bw_bold_kernel(const float* __restrict__ noise,
                    const float* __restrict__ sigma_p,
                    const float* __restrict__ mu_p,
                    const float* __restrict__ lamb_p,
                    const float* __restrict__ beta_p,
                    const float* __restrict__ psi_p,
                    const float* __restrict__ phi_p,
                    const float* __restrict__ chi_p,
                    float* __restrict__ out,
                    int T)
{
    const int gid = blockIdx.x * blockDim.x + threadIdx.x;  // 0..B/2-1

    BWConst C;
    C.sigma = __ldg(sigma_p);
    C.mu    = __ldg(mu_p);
    const float lamb = __ldg(lamb_p);
    const float beta = __ldg(beta_p);
    C.psi   = __ldg(psi_p);
    C.phi   = __ldg(phi_p);
    C.chi   = __ldg(chi_p);
    C.c_vl  = DT_C / lamb;
    C.ib    = 1.0f / beta;
    C.l2mb  = log2f(1.0f - beta);

    BWState stx, sty;        // sims 2*gid and 2*gid+1
    bw_seed(stx, C);
    bw_seed(sty, C);

    const float2* np = (const float2*)(noise) + gid;   // noise[t*BS + 2*gid]
    float2*       op = (float2*)(out)         + gid;
    const int     S2 = BS / 2;                          // float2 row stride

    const int nch = T / U;

    float2 bufA[U], bufB[U];
    if (nch > 0) {
        #pragma unroll
        for (int i = 0; i < U; i++) bufA[i] = np[(size_t)i * S2];
    }

    int c = 0;
    for (; c + 1 < nch; c += 2) {
        {   // prefetch chunk c+1
            const float2* pp = np + (size_t)(c + 1) * U * S2;
            #pragma unroll
            for (int i = 0; i < U; i++) bufB[i] = pp[(size_t)i * S2];
        }
        {   // compute chunk c
            float2* o = op + (size_t)c * U * S2;
            #pragma unroll
            for (int i = 0; i < U; i++) {
                float2 y;
                y.x = bw_step(stx, C, bufA[i].x);
                y.y = bw_step(sty, C, bufA[i].y);
                o[(size_t)i * S2] = y;
            }
        }
        if (c + 2 < nch) {   // prefetch chunk c+2
            const float2* pp = np + (size_t)(c + 2) * U * S2;
            #pragma unroll
            for (int i = 0; i < U; i++) bufA[i] = pp[(size_t)i * S2];
        }
        {   // compute chunk c+1
            float2* o = op + (size_t)(c + 1) * U * S2;
            #pragma unroll
            for (int i = 0; i < U; i++) {
                float2 y;
                y.x = bw_step(stx, C, bufB[i].x);
                y.y = bw_step(sty, C, bufB[i].y);
                o[(size_t)i * S2] = y;
            }
        }
    }
    if (c < nch) {  // odd trailing chunk
        float2* o = op + (size_t)c * U * S2;
        #pragma unroll
        for (int i = 0; i < U; i++) {
            float2 y;
            y.x = bw_step(stx, C, bufA[i].x);
            y.y = bw_step(sty, C, bufA[i].y);
            o[(size_t)i * S2] = y;
        }
        c++;
    }

    // Tail (T not divisible by U).
    for (int t = nch * U; t < T; t++) {
        const float2 z = np[(size_t)t * S2];
        float2 y;
        y.x = bw_step(stx, C, z.x);
        y.y = bw_step(sty, C, z.y);
        op[(size_t)t * S2] = y;
    }
}

extern "C" void kernel_launch(void* const* d_in, const int* in_sizes, int n_in,
                              void* d_out, int out_size)
{
    const float* noise = (const float*)d_in[0];
    const int T = in_sizes[0] / BATCH_C;

    const int threads = 64;                    // 2 warps -> SMSP 0,1
    const int blocks  = (BATCH_C / 2) / threads;  // 128 blocks over 128 SMs

    bw_bold_kernel<10, BATCH_C><<<blocks, threads>>>(
        noise,
        (const float*)d_in[1], (const float*)d_in[2],
        (const float*)d_in[3], (const float*)d_in[4],
        (const float*)d_in[5], (const float*)d_in[6],
        (const float*)d_in[7],
        (float*)d_out, T);
}

// round 5
// speedup vs baseline: 1.0769x; 1.0769x over previous
#include <cuda_runtime.h>
#include <cuda_bf16.h>

// Balloon-Windkessel BOLD, explicit Euler, T=1000 steps, B=16384 sims.
// R5: packed f32x2 arithmetic (SASS FFMA2), 2 sims per thread.
//
// Why: the kernel is FMA-issue-rate bound (FFMA rt_SMSP=2). Packing two
// sims into f32x2 halves FMA-class issue slots per sim-step. Every packed
// lane is IEEE-rn, and all subs/negs are expressed as fma/add forms that
// round identically to the R1 scalar ops -> bit-identical results
// (rel_err 1.38994e-4).
//
// Memory: noise/output accessed as 64-bit words (two adjacent sims), so
// packing is free. Ping-pong register prefetch (U=10 chunks).

#define DT_C        0.01f
#define V0_C        0.02f
#define NOISE_AMP_C 0.01f
#define BATCH_C     16384

typedef unsigned long long u64;

__device__ __forceinline__ float fast_rcp(float x) {
    float r; asm("rcp.approx.f32 %0, %1;" : "=f"(r) : "f"(x)); return r;
}
__device__ __forceinline__ float fast_ex2(float x) {
    float r; asm("ex2.approx.f32 %0, %1;" : "=f"(r) : "f"(x)); return r;
}
__device__ __forceinline__ u64 pk(float x, float y) {
    u64 r; asm("mov.b64 %0, {%1, %2};" : "=l"(r) : "f"(x), "f"(y)); return r;
}
__device__ __forceinline__ void upk(u64 v, float& x, float& y) {
    asm("mov.b64 {%0, %1}, %2;" : "=f"(x), "=f"(y) : "l"(v));
}
__device__ __forceinline__ u64 pfma(u64 a, u64 b, u64 c) {
    u64 d; asm("fma.rn.f32x2 %0, %1, %2, %3;" : "=l"(d) : "l"(a), "l"(b), "l"(c));
    return d;
}
__device__ __forceinline__ u64 pmul(u64 a, u64 b) {
    u64 d; asm("mul.rn.f32x2 %0, %1, %2;" : "=l"(d) : "l"(a), "l"(b));
    return d;
}
__device__ __forceinline__ u64 padd(u64 a, u64 b) {
    u64 d; asm("add.rn.f32x2 %0, %1, %2;" : "=l"(d) : "l"(a), "l"(b));
    return d;
}

struct PConst {
    u64 dt, na, cvl, ib2, negmu, negsigma;
    u64 neg1, one, zero, negone;
    u64 psi2, phi2, chi2, v02;
    float l2mb;
};

struct PState {
    u64 s, f, v, q, negq;     // negq = exact -q
    u64 E, fm1, nss, fib;     // look-aheads for current f,s
};

// One packed Euler step (both sims). Each lane bit-identical to R1's scalar step.
__device__ __forceinline__ u64 bw_step(PState& st, const PConst& C, u64 z)
{
    // f - v  == rn(-1*v + f)  (identical to FSUB rn)
    const u64 fmv = pfma(C.neg1, st.v, st.f);
    const u64 v2  = pfma(C.cvl, fmv, st.v);
    const u64 in1 = pfma(C.negmu, st.fm1, st.nss);
    const u64 in2 = pfma(C.na, z, in1);
    const u64 s2  = pfma(C.dt, in2, st.s);
    const u64 f2  = pfma(C.dt, st.s, st.f);
    const u64 qin = pfma(st.fib, st.E, st.negq);   // fmaf(fib, E, -q)
    const u64 q2  = pfma(C.cvl, qin, st.q);
    const u64 nq2 = pfma(C.neg1, q2, C.zero);      // exact -q2

    // Look-aheads for next step (pure functions of s2/f2; same ops as R1):
    float f2x, f2y; upk(f2, f2x, f2y);
    const float ex = 1.0f - fast_ex2(C.l2mb * fast_rcp(f2x));
    const float ey = 1.0f - fast_ex2(C.l2mb * fast_rcp(f2y));
    st.E   = pk(ex, ey);
    st.fm1 = padd(f2, C.negone);                   // rn(f2 + (-1)) == f2-1
    st.nss = pmul(C.negsigma, s2);                 // rn(-sigma*s2)
    st.fib = pmul(C.ib2, f2);

    // BOLD readout (identical rounding to R1):
    float v2x, v2y; upk(v2, v2x, v2y);
    const u64 rv = pk(fast_rcp(v2x), fast_rcp(v2y));
    const u64 a  = pfma(C.neg1, q2, C.one);        // 1 - q2
    const u64 b  = pfma(nq2, rv, C.one);           // fmaf(-q2, rv, 1)
    const u64 cm = pfma(C.neg1, v2, C.one);        // 1 - v2
    const u64 d  = pmul(C.chi2, cm);               // chi*(1-v2)
    const u64 e2 = pfma(C.psi2, b, d);
    const u64 g  = pfma(C.phi2, a, e2);
    const u64 y  = pmul(C.v02, g);                 // V0 * (...)

    st.s = s2; st.f = f2; st.v = v2; st.q = q2; st.negq = nq2;
    return y;
}

template<int U, int BS>
__global__ __launch_bounds__(64, 1)
void bw_bold_kernel(const float* __restrict__ noise,
                    const float* __restrict__ sigma_p,
                    const float* __restrict__ mu_p,
                    const float* __restrict__ lamb_p,
                    const float* __restrict__ beta_p,
                    const float* __restrict__ psi_p,
                    const float* __restrict__ phi_p,
                    const float* __restrict__ chi_p,
                    float* __restrict__ out,
                    int T)
{
    const int gid = blockIdx.x * blockDim.x + threadIdx.x;  // 0..B/2-1

    const float sigma = __ldg(sigma_p);
    const float mu    = __ldg(mu_p);
    const float lamb  = __ldg(lamb_p);
    const float beta  = __ldg(beta_p);
    const float psi   = __ldg(psi_p);
    const float phi   = __ldg(phi_p);
    const float chi   = __ldg(chi_p);

    const float c_vl = DT_C / lamb;
    const float ib   = 1.0f / beta;

    PConst C;
    C.dt       = pk(DT_C, DT_C);
    C.na       = pk(NOISE_AMP_C, NOISE_AMP_C);
    C.cvl      = pk(c_vl, c_vl);
    C.ib2      = pk(ib, ib);
    C.negmu    = pk(-mu, -mu);
    C.negsigma = pk(-sigma, -sigma);
    C.neg1     = pk(-1.0f, -1.0f);
    C.one      = pk(1.0f, 1.0f);
    C.zero     = pk(0.0f, 0.0f);
    C.negone   = pk(-1.0f, -1.0f);
    C.psi2     = pk(psi, psi);
    C.phi2     = pk(phi, phi);
    C.chi2     = pk(chi, chi);
    C.v02      = pk(V0_C, V0_C);
    C.l2mb     = log2f(1.0f - beta);

    // Initial state + seeded look-aheads (same ops as R1's first step).
    PState st;
    st.s = C.zero; st.f = C.one; st.v = C.one; st.q = C.one;
    st.negq = C.neg1;
    {
        const float e0 = 1.0f - fast_ex2(C.l2mb * fast_rcp(1.0f));
        st.E   = pk(e0, e0);
        st.fm1 = C.zero;                 // 1 - 1
        st.nss = pk(-sigma * 0.0f, -sigma * 0.0f);
        st.fib = pk(1.0f * ib, 1.0f * ib);
    }

    // 64-bit packed views: columns (2*gid, 2*gid+1) of each row.
    const u64* np = (const u64*)noise + gid;
    u64*       op = (u64*)out         + gid;
    const int  S2 = BS / 2;

    const int nch = T / U;

    u64 bufA[U], bufB[U];
    if (nch > 0) {
        #pragma unroll
        for (int i = 0; i < U; i++) bufA[i] = np[(size_t)i * S2];
    }

    int c = 0;
    for (; c + 1 < nch; c += 2) {
        {   // prefetch chunk c+1
            const u64* pp = np + (size_t)(c + 1) * U * S2;
            #pragma unroll
            for (int i = 0; i < U; i++) bufB[i] = pp[(size_t)i * S2];
        }
        {   // compute chunk c
            u64* o = op + (size_t)c * U * S2;
            #pragma unroll
            for (int i = 0; i < U; i++)
                o[(size_t)i * S2] = bw_step(st, C, bufA[i]);
        }
        if (c + 2 < nch) {   // prefetch chunk c+2
            const u64* pp = np + (size_t)(c + 2) * U * S2;
            #pragma unroll
            for (int i = 0; i < U; i++) bufA[i] = pp[(size_t)i * S2];
        }
        {   // compute chunk c+1
            u64* o = op + (size_t)(c + 1) * U * S2;
            #pragma unroll
            for (int i = 0; i < U; i++)
                o[(size_t)i * S2] = bw_step(st, C, bufB[i]);
        }
    }
    if (c < nch) {  // odd trailing chunk
        u64* o = op + (size_t)c * U * S2;
        #pragma unroll
        for (int i = 0; i < U; i++)
            o[(size_t)i * S2] = bw_step(st, C, bufA[i]);
        c++;
    }

    // Tail (T not divisible by U).
    for (int t = nch * U; t < T; t++) {
        op[(size_t)t * S2] = bw_step(st, C, np[(size_t)t * S2]);
    }
}

extern "C" void kernel_launch(void* const* d_in, const int* in_sizes, int n_in,
                              void* d_out, int out_size)
{
    const float* noise = (const float*)d_in[0];
    const int T = in_sizes[0] / BATCH_C;

    // B/2 = 8192 threads; 64-thread blocks -> 128 blocks over 128 SMs,
    // 2 warps/SM (SMSP 0,1) to spread LSU/L1 pressure.
    const int threads = 64;
    const int blocks  = (BATCH_C / 2) / threads;

    bw_bold_kernel<10, BATCH_C><<<blocks, threads>>>(
        noise,
        (const float*)d_in[1], (const float*)d_in[2],
        (const float*)d_in[3], (const float*)d_in[4],
        (const float*)d_in[5], (const float*)d_in[6],
        (const float*)d_in[7],
        (float*)d_out, T);
}

// round 6
// speedup vs baseline: 2.0685x; 1.9209x over previous
#include <cuda_runtime.h>
#include <cuda_bf16.h>

// Balloon-Windkessel BOLD, explicit Euler, T=1000 steps, B=16384 sims.
// R6 = R3 (best: 59.4us) with FMA-pipe op count cut 20 -> ~17:
//  - state recurrences (s,f,v,q) BIT-IDENTICAL to R1/R3 (accumulating paths
//    untouched; rel_err floor 1.39e-4 from approx MUFU only).
//  - BOLD readout refactored to 4 FMA-class ops with precomputed constants
//    (non-loop-carried => one-shot rounding, est. +~2e-4 rel_err, safe).
//  - s-drive in1 = fma(-mu, f-1, -sigma*s) staged in the look-ahead
//    (pure function of finalized s2,f2; identical instructions).
// Rationale: per-SMSP FFMA rt=2 is the binding constraint at 1 warp/SMSP
// (512 warps fixed by B). Fewer FMA-pipe ops/step is the only lever.

#define DT_C        0.01f
#define V0_C        0.02f
#define NOISE_AMP_C 0.01f
#define BATCH_C     16384

__device__ __forceinline__ float fast_rcp(float x) {
    float r; asm("rcp.approx.f32 %0, %1;" : "=f"(r) : "f"(x)); return r;
}
__device__ __forceinline__ float fast_ex2(float x) {
    float r; asm("ex2.approx.f32 %0, %1;" : "=f"(r) : "f"(x)); return r;
}

struct BWState {
    float s, f, v, q;
    float E;    // 1 - (1-beta)^(1/f)  (for current f)
    float fib;  // f * (1/beta)
    float in1;  // fma(-mu, f-1, -sigma*s)  (s-drive, staged)
};

struct BWConst {
    float sigma, mu, ib, c_vl, l2mb;
    float C0, C1, C2, C3;   // readout constants
};

// One Euler step. State arithmetic identical to R1/R3; readout refactored.
__device__ __forceinline__ float bw_step(BWState& st, const BWConst& C, float z)
{
    const float s2 = fmaf(DT_C, fmaf(NOISE_AMP_C, z, st.in1), st.s);
    const float f2 = fmaf(DT_C, st.s, st.f);
    const float v2 = fmaf(C.c_vl, st.f - st.v, st.v);
    const float q2 = fmaf(C.c_vl, fmaf(st.fib, st.E, -st.q), st.q);

    // Look-aheads for the next step (pure functions of s2, f2):
    const float rf  = fast_rcp(f2);
    st.E   = 1.0f - fast_ex2(C.l2mb * rf);
    st.fib = f2 * C.ib;
    st.in1 = fmaf(-C.mu, f2 - 1.0f, -C.sigma * s2);

    // Readout: y = C0 - C1*q2 - C3*v2 - (C2*q2)*rcp(v2)   (4 FMA-class ops)
    const float rv = fast_rcp(v2);
    const float t0 = fmaf(-C.C3, v2, C.C0);
    const float t1 = fmaf(-C.C1, q2, t0);
    const float y  = fmaf(-C.C2 * q2, rv, t1);

    st.s = s2; st.f = f2; st.v = v2; st.q = q2;
    return y;
}

template<int U, int BS>
__global__ __launch_bounds__(128, 1)
void bw_bold_kernel(const float* __restrict__ noise,
                    const float* __restrict__ sigma_p,
                    const float* __restrict__ mu_p,
                    const float* __restrict__ lamb_p,
                    const float* __restrict__ beta_p,
                    const float* __restrict__ psi_p,
                    const float* __restrict__ phi_p,
                    const float* __restrict__ chi_p,
                    float* __restrict__ out,
                    int T)
{
    const int gid = blockIdx.x * blockDim.x + threadIdx.x;

    BWConst C;
    C.sigma = __ldg(sigma_p);
    C.mu    = __ldg(mu_p);
    const float lamb = __ldg(lamb_p);
    const float beta = __ldg(beta_p);
    const float psi  = __ldg(psi_p);
    const float phi  = __ldg(phi_p);
    const float chi  = __ldg(chi_p);
    C.c_vl  = DT_C / lamb;
    C.ib    = 1.0f / beta;
    C.l2mb  = log2f(1.0f - beta);
    C.C0    = V0_C * (phi + psi + chi);
    C.C1    = V0_C * phi;
    C.C2    = V0_C * psi;
    C.C3    = V0_C * chi;

    BWState st;
    st.s = 0.0f; st.f = 1.0f; st.v = 1.0f; st.q = 1.0f;
    {
        const float rf = fast_rcp(st.f);
        st.E   = 1.0f - fast_ex2(C.l2mb * rf);
        st.fib = st.f * C.ib;
        st.in1 = fmaf(-C.mu, st.f - 1.0f, -C.sigma * st.s);
    }

    const float* np = noise + gid;
    float*       op = out   + gid;

    const int nch = T / U;

    float bufA[U], bufB[U];
    if (nch > 0) {
        #pragma unroll
        for (int i = 0; i < U; i++) bufA[i] = np[(size_t)i * BS];
    }

    int c = 0;
    for (; c + 1 < nch; c += 2) {
        {   // prefetch chunk c+1
            const float* pp = np + (size_t)(c + 1) * U * BS;
            #pragma unroll
            for (int i = 0; i < U; i++) bufB[i] = pp[(size_t)i * BS];
        }
        {   // compute chunk c
            float* o = op + (size_t)c * U * BS;
            #pragma unroll
            for (int i = 0; i < U; i++)
                o[(size_t)i * BS] = bw_step(st, C, bufA[i]);
        }
        if (c + 2 < nch) {   // prefetch chunk c+2
            const float* pp = np + (size_t)(c + 2) * U * BS;
            #pragma unroll
            for (int i = 0; i < U; i++) bufA[i] = pp[(size_t)i * BS];
        }
        {   // compute chunk c+1
            float* o = op + (size_t)(c + 1) * U * BS;
            #pragma unroll
            for (int i = 0; i < U; i++)
                o[(size_t)i * BS] = bw_step(st, C, bufB[i]);
        }
    }
    if (c < nch) {  // odd trailing chunk
        float* o = op + (size_t)c * U * BS;
        #pragma unroll
        for (int i = 0; i < U; i++)
            o[(size_t)i * BS] = bw_step(st, C, bufA[i]);
        c++;
    }

    // Tail (T not divisible by U).
    for (int t = nch * U; t < T; t++) {
        op[(size_t)t * BS] = bw_step(st, C, np[(size_t)t * BS]);
    }
}

extern "C" void kernel_launch(void* const* d_in, const int* in_sizes, int n_in,
                              void* d_out, int out_size)
{
    const float* noise = (const float*)d_in[0];
    const int T = in_sizes[0] / BATCH_C;

    const int threads = 128;
    const int blocks  = BATCH_C / threads;   // 128 blocks x 128 thr = 1 warp/SMSP

    bw_bold_kernel<20, BATCH_C><<<blocks, threads>>>(
        noise,
        (const float*)d_in[1], (const float*)d_in[2],
        (const float*)d_in[3], (const float*)d_in[4],
        (const float*)d_in[5], (const float*)d_in[6],
        (const float*)d_in[7],
        (float*)d_out, T);
}

// round 7
// speedup vs baseline: 2.2220x; 1.0742x over previous
#include <cuda_runtime.h>
#include <cuda_bf16.h>

// Balloon-Windkessel BOLD, explicit Euler, T=1000 steps, B=16384 sims.
// R7 = R6 (57.4us) with the E(f) transcendental replaced by a degree-7
// Taylor polynomial of G(u) = f*E(f)/beta in u = f-1:
//  - coefficients computed once per thread in double precision from beta
//    (exp-of-power-series ODE recurrence) -> no hardcoded parameters.
//  - per-step MUFU drops 3 -> 1 (only rcp(v2) in the readout); the 41-cycle
//    rcp->ex2 dependency chain disappears (7-FMA Horner, 1 step of slack).
//  - s,f,v,q update forms unchanged from R1/R6 (carried rounding preserved);
//    only the q-drive value shifts by <~1e-6 (damped, non-accumulating).

#define DT_C        0.01f
#define V0_C        0.02f
#define NOISE_AMP_C 0.01f
#define BATCH_C     16384

__device__ __forceinline__ float fast_rcp(float x) {
    float r; asm("rcp.approx.f32 %0, %1;" : "=f"(r) : "f"(x)); return r;
}

struct BWState {
    float s, f, v, q;
    float G;    // f*E(f)/beta for current f (staged one step ahead)
    float in1;  // fma(-mu, f-1, -sigma*s)  (s-drive, staged)
};

struct BWConst {
    float sigma, mu, c_vl;
    float C0, C1, C2, C3;            // readout constants
    float g0,g1,g2,g3,g4,g5,g6,g7;   // G(u) Taylor coefficients
};

__device__ __forceinline__ float eval_G(const BWConst& C, float u) {
    float p = C.g7;
    p = fmaf(p, u, C.g6);
    p = fmaf(p, u, C.g5);
    p = fmaf(p, u, C.g4);
    p = fmaf(p, u, C.g3);
    p = fmaf(p, u, C.g2);
    p = fmaf(p, u, C.g1);
    p = fmaf(p, u, C.g0);
    return p;
}

// One Euler step. Carried-state arithmetic identical to R1/R6.
__device__ __forceinline__ float bw_step(BWState& st, const BWConst& C, float z)
{
    const float s2 = fmaf(DT_C, fmaf(NOISE_AMP_C, z, st.in1), st.s);
    const float f2 = fmaf(DT_C, st.s, st.f);
    const float v2 = fmaf(C.c_vl, st.f - st.v, st.v);
    const float q2 = fmaf(C.c_vl, st.G - st.q, st.q);

    // Look-aheads for the next step (pure functions of s2, f2):
    const float u = f2 - 1.0f;
    st.G   = eval_G(C, u);
    st.in1 = fmaf(-C.mu, u, -C.sigma * s2);

    // Readout: y = C0 - C1*q2 - C3*v2 - (C2*q2)*rcp(v2)
    const float rv = fast_rcp(v2);
    const float t0 = fmaf(-C.C3, v2, C.C0);
    const float t1 = fmaf(-C.C1, q2, t0);
    const float y  = fmaf(-C.C2 * q2, rv, t1);

    st.s = s2; st.f = f2; st.v = v2; st.q = q2;
    return y;
}

template<int U, int BS>
__global__ __launch_bounds__(128, 1)
void bw_bold_kernel(const float* __restrict__ noise,
                    const float* __restrict__ sigma_p,
                    const float* __restrict__ mu_p,
                    const float* __restrict__ lamb_p,
                    const float* __restrict__ beta_p,
                    const float* __restrict__ psi_p,
                    const float* __restrict__ phi_p,
                    const float* __restrict__ chi_p,
                    float* __restrict__ out,
                    int T)
{
    const int gid = blockIdx.x * blockDim.x + threadIdx.x;

    BWConst C;
    C.sigma = __ldg(sigma_p);
    C.mu    = __ldg(mu_p);
    const float lamb = __ldg(lamb_p);
    const float beta = __ldg(beta_p);
    const float psi  = __ldg(psi_p);
    const float phi  = __ldg(phi_p);
    const float chi  = __ldg(chi_p);
    C.c_vl  = DT_C / lamb;
    C.C0    = V0_C * (phi + psi + chi);
    C.C1    = V0_C * phi;
    C.C2    = V0_C * psi;
    C.C3    = V0_C * chi;

    // --- One-time double-precision Taylor coefficients ---
    // E(f) = 1 - exp(c/f), c = ln(1-beta), f = 1+u.
    // a(u) = c*(1/(1+u) - 1) = sum_{k>=1} c*(-1)^k u^k
    // A(u) = exp(a(u)) via series ODE: (k+1)A[k+1] = sum_j (j+1) a[j+1] A[k-j]
    // E-coeffs: e0 = 1-(1-beta)*A0 ; ek = -(1-beta)*Ak
    // G(u) = (1+u)*E(u)/beta: gk = (ek + e(k-1))/beta.
    {
        const double bd  = (double)beta;
        const double c   = log(1.0 - bd);
        const double omb = 1.0 - bd;
        double a[8], A[8], e[8];
        a[0] = 0.0;
        #pragma unroll
        for (int k = 1; k < 8; k++) a[k] = (k & 1) ? -c : c;
        A[0] = 1.0;
        #pragma unroll
        for (int k = 0; k < 7; k++) {
            double sum = 0.0;
            #pragma unroll
            for (int j = 0; j <= k; j++) sum += (double)(j + 1) * a[j + 1] * A[k - j];
            A[k + 1] = sum / (double)(k + 1);
        }
        e[0] = 1.0 - omb * A[0];
        #pragma unroll
        for (int k = 1; k < 8; k++) e[k] = -omb * A[k];
        const double ibd = 1.0 / bd;
        C.g0 = (float)(e[0] * ibd);
        C.g1 = (float)((e[1] + e[0]) * ibd);
        C.g2 = (float)((e[2] + e[1]) * ibd);
        C.g3 = (float)((e[3] + e[2]) * ibd);
        C.g4 = (float)((e[4] + e[3]) * ibd);
        C.g5 = (float)((e[5] + e[4]) * ibd);
        C.g6 = (float)((e[6] + e[5]) * ibd);
        C.g7 = (float)((e[7] + e[6]) * ibd);
    }

    BWState st;
    st.s = 0.0f; st.f = 1.0f; st.v = 1.0f; st.q = 1.0f;
    st.G   = eval_G(C, 0.0f);
    st.in1 = fmaf(-C.mu, 0.0f, -C.sigma * 0.0f);

    const float* np = noise + gid;
    float*       op = out   + gid;

    const int nch = T / U;

    float bufA[U], bufB[U];
    if (nch > 0) {
        #pragma unroll
        for (int i = 0; i < U; i++) bufA[i] = np[(size_t)i * BS];
    }

    int c = 0;
    for (; c + 1 < nch; c += 2) {
        {   // prefetch chunk c+1
            const float* pp = np + (size_t)(c + 1) * U * BS;
            #pragma unroll
            for (int i = 0; i < U; i++) bufB[i] = pp[(size_t)i * BS];
        }
        {   // compute chunk c
            float* o = op + (size_t)c * U * BS;
            #pragma unroll
            for (int i = 0; i < U; i++)
                o[(size_t)i * BS] = bw_step(st, C, bufA[i]);
        }
        if (c + 2 < nch) {   // prefetch chunk c+2
            const float* pp = np + (size_t)(c + 2) * U * BS;
            #pragma unroll
            for (int i = 0; i < U; i++) bufA[i] = pp[(size_t)i * BS];
        }
        {   // compute chunk c+1
            float* o = op + (size_t)(c + 1) * U * BS;
            #pragma unroll
            for (int i = 0; i < U; i++)
                o[(size_t)i * BS] = bw_step(st, C, bufB[i]);
        }
    }
    if (c < nch) {  // odd trailing chunk
        float* o = op + (size_t)c * U * BS;
        #pragma unroll
        for (int i = 0; i < U; i++)
            o[(size_t)i * BS] = bw_step(st, C, bufA[i]);
        c++;
    }

    // Tail (T not divisible by U).
    for (int t = nch * U; t < T; t++) {
        op[(size_t)t * BS] = bw_step(st, C, np[(size_t)t * BS]);
    }
}

extern "C" void kernel_launch(void* const* d_in, const int* in_sizes, int n_in,
                              void* d_out, int out_size)
{
    const float* noise = (const float*)d_in[0];
    const int T = in_sizes[0] / BATCH_C;

    const int threads = 128;
    const int blocks  = BATCH_C / threads;   // 128 blocks x 128 thr = 1 warp/SMSP

    bw_bold_kernel<20, BATCH_C><<<blocks, threads>>>(
        noise,
        (const float*)d_in[1], (const float*)d_in[2],
        (const float*)d_in[3], (const float*)d_in[4],
        (const float*)d_in[5], (const float*)d_in[6],
        (const float*)d_in[7],
        (float*)d_out, T);
}